// round 1
// baseline (speedup 1.0000x reference)
#include <cuda_runtime.h>
#include <math.h>

// Problem constants
#define NCg    64
#define Cg     256
#define Dg     32
#define Kg     16
#define KBg    16
#define ALPHAg 16
#define Bg     16
#define HSg    128
#define HMg    128
#define HMODg  32
#define BSg    8
#define NTOT   (NCg*Cg)          // 16384
#define MODIN  113
#define MODINP 116               // padded to multiple of 4
#define MODOUT 65

// Output layout: readout | h_new | msg | heb | heb_b (flattened, row-major)
#define OFF_READOUT 0
#define OFF_HNEW   (BSg*NCg*Dg)                 // 16384
#define OFF_MSG    (OFF_HNEW + BSg*NTOT*Dg)     // +4194304
#define OFF_HEB    (OFF_MSG  + BSg*NTOT*Dg)     // +4194304
#define OFF_HEBB   (OFF_HEB  + BSg*NTOT*Kg)     // +2097152

struct __align__(16) Smem {
    float in[BSg*MODINP];                 // mod_input rows (padded to 116, zeros in pad)
    union {
        struct { float w1[HMODg*MODINP]; float w2[HMODg*MODOUT]; } mod;  // per-neuron weights
        float wt[128*100];                // staged shared MLP w1 (rows padded to 100)
    } u;
    float hid[BSg*HMODg];                 // mod hidden (tanh)
    float outb[BSg*66];                   // mod output (65, padded row 66)
    float neigh[BSg*Kg*33];               // gathered neighbors (pad 33)
    float bneigh[BSg*KBg*33];             // gathered border neighbors
    float wsig[BSg*Kg];
    float wsigb[BSg*KBg];
    float sin_[BSg*100];                  // state MLP input  [h|agg|prim|decay|0,0,0]
    float min_[BSg*100];                  // msg MLP input    [h_new|agg|nid|0..0]
    float hbuf[BSg*HSg];                  // shid / mhid (reused)
    float msg[BSg*33];
    int conn[Kg];
    int bconn[KBg];
};

__device__ __forceinline__ float sigmoidf_(float x) {
    return 1.f / (1.f + __expf(-x));
}

__global__ void __launch_bounds__(256, 2)
cell_kernel(const float* __restrict__ x,
            const float* __restrict__ h_in,
            const float* __restrict__ prevmsg,
            const float* __restrict__ decay_logit,
            const float* __restrict__ prim,
            const float* __restrict__ heb_tr,
            const float* __restrict__ heb_trb,
            const float* __restrict__ state_w1, const float* __restrict__ state_b1,
            const float* __restrict__ state_w2, const float* __restrict__ state_b2,
            const float* __restrict__ msg_w1,  const float* __restrict__ msg_b1,
            const float* __restrict__ msg_w2,  const float* __restrict__ msg_b2,
            const float* __restrict__ mod_w1,  const float* __restrict__ mod_b1,
            const float* __restrict__ mod_w2,  const float* __restrict__ mod_b2,
            const float* __restrict__ neuron_id,
            const int*   __restrict__ conn_idx,
            const int*   __restrict__ bconn_idx,
            float* __restrict__ dout)
{
    extern __shared__ char smraw[];
    Smem& s = *reinterpret_cast<Smem*>(smraw);
    const int tid = threadIdx.x;
    const int n  = blockIdx.x;
    const int nc = n >> 8;
    const int c  = n & 255;
    const bool bord = (c >= ALPHAg) && (c < ALPHAg + Bg);

    // ---------------- Phase A: stage mod_input, per-neuron weights, indices -------------
    for (int idx = tid; idx < BSg*MODINP; idx += 256) {
        int b = idx / MODINP, i = idx - b*MODINP;
        int base = ((b*NCg + nc)*Cg + c);
        float v = 0.f;
        if (i < Kg)       v = heb_tr[base*Kg + i];
        else if (i < 48)  { int d = i - 16; v = h_in[base*Dg + d];
                            if (c < ALPHAg) v += x[b*(NCg*Dg) + nc*Dg + d]; }
        else if (i == 48) v = decay_logit[base];
        else if (i < 81)  v = prim[base*Dg + (i-49)];
        else if (i < MODIN) v = neuron_id[(nc*Cg+c)*Dg + (i-81)];
        s.in[idx] = v;
    }
    for (int idx = tid; idx < HMODg*MODINP; idx += 256) {
        int o = idx / MODINP, i = idx - o*MODINP;
        s.u.mod.w1[idx] = (i < MODIN) ? mod_w1[(n*HMODg + o)*MODIN + i] : 0.f;
    }
    for (int idx = tid; idx < HMODg*MODOUT; idx += 256)
        s.u.mod.w2[idx] = mod_w2[n*HMODg*MODOUT + idx];
    if (tid < Kg) s.conn[tid] = conn_idx[(nc*Cg+c)*Kg + tid];
    if (bord && tid >= 32 && tid < 32+KBg)
        s.bconn[tid-32] = bconn_idx[(nc*Bg + (c-ALPHAg))*KBg + (tid-32)];
    __syncthreads();

    // ---------------- Phase B: hid = tanh(mod_w1 @ in + b1)  (float4 dot) ---------------
    {
        int o = tid >> 3, b = tid & 7;
        const float4* w4 = reinterpret_cast<const float4*>(s.u.mod.w1 + o*MODINP);
        const float4* x4 = reinterpret_cast<const float4*>(s.in + b*MODINP);
        float acc = mod_b1[n*HMODg + o];
        #pragma unroll
        for (int j = 0; j < MODINP/4; ++j) {
            float4 w = w4[j]; float4 xx = x4[j];
            acc += w.x*xx.x + w.y*xx.y + w.z*xx.z + w.w*xx.w;
        }
        s.hid[b*HMODg + o] = tanhf(acc);
    }
    // ---------------- Phase D (overlapped): gather neighbors ----------------------------
    for (int idx = tid; idx < BSg*Kg*Dg; idx += 256) {
        int d = idx & 31, k = (idx >> 5) & 15, b = idx >> 9;
        s.neigh[(b*Kg + k)*33 + d] = prevmsg[((b*NCg + nc)*Cg + s.conn[k])*Dg + d];
    }
    if (bord) {
        for (int idx = tid; idx < BSg*KBg*Dg; idx += 256) {
            int d = idx & 31, k = (idx >> 5) & 15, b = idx >> 9;
            int j = s.bconn[k];
            s.bneigh[(b*KBg + k)*33 + d] =
                prevmsg[((b*NCg + (j >> 4))*Cg + ALPHAg + (j & 15))*Dg + d];
        }
    }
    __syncthreads();

    // ---------------- Phase C: out = hid @ mod_w2 + b2 ----------------------------------
    for (int t = tid; t < BSg*MODOUT; t += 256) {
        int b = t & 7, o2 = t >> 3;
        float acc = mod_b2[n*MODOUT + o2];
        #pragma unroll
        for (int hh = 0; hh < HMODg; ++hh)
            acc += s.hid[b*HMODg + hh] * s.u.mod.w2[hh*MODOUT + o2];
        s.outb[b*66 + o2] = acc;
    }
    __syncthreads();

    // ---------------- Phase E: w_sig, sin_/min_ prep, stage state_w1 --------------------
    if (tid < 128) {
        int b = tid >> 4, k = tid & 15;
        s.wsig[b*Kg + k] = sigmoidf_(s.outb[b*66 + k] + s.in[b*MODINP + k]);
    } else if (bord) {
        int t = tid - 128; int b = t >> 4, k = t & 15;
        float v = s.outb[b*66 + 16 + k]
                + heb_trb[((b*NCg + nc)*Bg + (c - ALPHAg))*KBg + k];
        s.wsigb[b*KBg + k] = sigmoidf_(v);
    }
    for (int t = tid; t < BSg*100; t += 256) {
        int b = t / 100, j = t - b*100;
        float v, m;
        if (j < 32)       { v = s.in[b*MODINP + 16 + j]; m = 0.f; }       // h ; h_new later
        else if (j < 64)  { v = 0.f; m = 0.f; }                            // agg later
        else if (j < 96)  { v = s.outb[b*66 + 33 + (j-64)];                // new_prim
                            m = s.in[b*MODINP + 81 + (j-64)]; }            // nid
        else if (j == 96) { v = s.outb[b*66 + 32]; m = 0.f; }              // new_decay
        else              { v = 0.f; m = 0.f; }
        s.sin_[t] = v;
        s.min_[t] = m;
    }
    // stage state_w1 into wt (rows padded 97 -> 100)
    for (int idx = tid; idx < HSg*97; idx += 256) {
        int hh = idx / 97, i = idx - hh*97;
        s.u.wt[hh*100 + i] = state_w1[idx];
    }
    for (int hh = tid; hh < HSg; hh += 256) {
        s.u.wt[hh*100 + 97] = 0.f; s.u.wt[hh*100 + 98] = 0.f; s.u.wt[hh*100 + 99] = 0.f;
    }
    __syncthreads();

    // ---------------- Phase F: agg ------------------------------------------------------
    {
        int b = tid >> 5, d = tid & 31;
        float acc = 0.f;
        #pragma unroll
        for (int k = 0; k < Kg; ++k)
            acc += s.wsig[b*Kg + k] * s.neigh[(b*Kg + k)*33 + d];
        if (bord) {
            #pragma unroll
            for (int k = 0; k < KBg; ++k)
                acc += s.wsigb[b*KBg + k] * s.bneigh[(b*KBg + k)*33 + d];
        }
        s.sin_[b*100 + 32 + d] = acc;
        s.min_[b*100 + 32 + d] = acc;
    }
    __syncthreads();

    // ---------------- Phase G: shid = tanh(state_w1 @ sin + b1) -------------------------
    {
        int b = tid >> 5, hg = tid & 31;          // thread computes 4 hidden units
        float a0 = state_b1[hg*4+0], a1 = state_b1[hg*4+1];
        float a2 = state_b1[hg*4+2], a3 = state_b1[hg*4+3];
        const float4* w0 = reinterpret_cast<const float4*>(s.u.wt + (hg*4+0)*100);
        const float4* w1p = reinterpret_cast<const float4*>(s.u.wt + (hg*4+1)*100);
        const float4* w2p = reinterpret_cast<const float4*>(s.u.wt + (hg*4+2)*100);
        const float4* w3p = reinterpret_cast<const float4*>(s.u.wt + (hg*4+3)*100);
        const float4* xin = reinterpret_cast<const float4*>(s.sin_ + b*100);
        for (int j = 0; j < 25; ++j) {
            float4 xx = xin[j];
            float4 w;
            w = w0[j];  a0 += w.x*xx.x + w.y*xx.y + w.z*xx.z + w.w*xx.w;
            w = w1p[j]; a1 += w.x*xx.x + w.y*xx.y + w.z*xx.z + w.w*xx.w;
            w = w2p[j]; a2 += w.x*xx.x + w.y*xx.y + w.z*xx.z + w.w*xx.w;
            w = w3p[j]; a3 += w.x*xx.x + w.y*xx.y + w.z*xx.z + w.w*xx.w;
        }
        s.hbuf[b*HSg + hg*4+0] = tanhf(a0);
        s.hbuf[b*HSg + hg*4+1] = tanhf(a1);
        s.hbuf[b*HSg + hg*4+2] = tanhf(a2);
        s.hbuf[b*HSg + hg*4+3] = tanhf(a3);
    }
    __syncthreads();

    // ---------------- Phase H: delta, h_new; stage msg_w1 -------------------------------
    {
        int b = tid >> 5, d = tid & 31;
        const float4* w4  = reinterpret_cast<const float4*>(state_w2 + d*HSg);
        const float4* hv4 = reinterpret_cast<const float4*>(s.hbuf + b*HSg);
        float acc = state_b2[d];
        #pragma unroll 8
        for (int j = 0; j < HSg/4; ++j) {
            float4 w = w4[j]; float4 hh = hv4[j];
            acc += w.x*hh.x + w.y*hh.y + w.z*hh.z + w.w*hh.w;
        }
        float dec = sigmoidf_(s.outb[b*66 + 32]);
        float hv  = s.in[b*MODINP + 16 + d];
        float hn  = dec*hv + (1.f - dec)*tanhf(acc);
        s.min_[b*100 + d] = hn;
        dout[OFF_HNEW + (((b*NCg + nc)*Cg + c)*Dg + d)] = hn;
    }
    // stage msg_w1 into wt (rows padded 96 -> 100)
    for (int idx = tid; idx < HMg*96; idx += 256) {
        int hh = idx / 96, i = idx - hh*96;
        s.u.wt[hh*100 + i] = msg_w1[idx];
    }
    for (int hh = tid; hh < HMg; hh += 256) {
        s.u.wt[hh*100 + 96] = 0.f; s.u.wt[hh*100 + 97] = 0.f;
        s.u.wt[hh*100 + 98] = 0.f; s.u.wt[hh*100 + 99] = 0.f;
    }
    __syncthreads();

    // ---------------- Phase I: mhid = tanh(msg_w1 @ min + b1) ---------------------------
    {
        int b = tid >> 5, hg = tid & 31;
        float a0 = msg_b1[hg*4+0], a1 = msg_b1[hg*4+1];
        float a2 = msg_b1[hg*4+2], a3 = msg_b1[hg*4+3];
        const float4* w0 = reinterpret_cast<const float4*>(s.u.wt + (hg*4+0)*100);
        const float4* w1p = reinterpret_cast<const float4*>(s.u.wt + (hg*4+1)*100);
        const float4* w2p = reinterpret_cast<const float4*>(s.u.wt + (hg*4+2)*100);
        const float4* w3p = reinterpret_cast<const float4*>(s.u.wt + (hg*4+3)*100);
        const float4* xin = reinterpret_cast<const float4*>(s.min_ + b*100);
        for (int j = 0; j < 25; ++j) {
            float4 xx = xin[j];
            float4 w;
            w = w0[j];  a0 += w.x*xx.x + w.y*xx.y + w.z*xx.z + w.w*xx.w;
            w = w1p[j]; a1 += w.x*xx.x + w.y*xx.y + w.z*xx.z + w.w*xx.w;
            w = w2p[j]; a2 += w.x*xx.x + w.y*xx.y + w.z*xx.z + w.w*xx.w;
            w = w3p[j]; a3 += w.x*xx.x + w.y*xx.y + w.z*xx.z + w.w*xx.w;
        }
        s.hbuf[b*HSg + hg*4+0] = tanhf(a0);
        s.hbuf[b*HSg + hg*4+1] = tanhf(a1);
        s.hbuf[b*HSg + hg*4+2] = tanhf(a2);
        s.hbuf[b*HSg + hg*4+3] = tanhf(a3);
    }
    __syncthreads();

    // ---------------- Phase J: msg -------------------------------------------------------
    {
        int b = tid >> 5, d = tid & 31;
        const float4* w4  = reinterpret_cast<const float4*>(msg_w2 + d*HMg);
        const float4* hv4 = reinterpret_cast<const float4*>(s.hbuf + b*HMg);
        float acc = msg_b2[d];
        #pragma unroll 8
        for (int j = 0; j < HMg/4; ++j) {
            float4 w = w4[j]; float4 hh = hv4[j];
            acc += w.x*hh.x + w.y*hh.y + w.z*hh.z + w.w*hh.w;
        }
        s.msg[b*33 + d] = acc;
        dout[OFF_MSG + (((b*NCg + nc)*Cg + c)*Dg + d)] = acc;
    }
    __syncthreads();

    // ---------------- Phase K: Hebbian updates ------------------------------------------
    if (tid < 128) {
        int b = tid >> 4, k = tid & 15;
        float dot = 0.f;
        #pragma unroll
        for (int d = 0; d < Dg; ++d)
            dot += s.msg[b*33 + d] * s.neigh[(b*Kg + k)*33 + d];
        float v = 0.9f * s.in[b*MODINP + k] + (0.1f/32.f) * dot;
        dout[OFF_HEB + (((b*NCg + nc)*Cg + c)*Kg + k)] = v;
    } else if (bord) {
        int t = tid - 128; int b = t >> 4, k = t & 15;
        float dot = 0.f;
        #pragma unroll
        for (int d = 0; d < Dg; ++d)
            dot += s.msg[b*33 + d] * s.bneigh[(b*KBg + k)*33 + d];
        float v = 0.9f * heb_trb[((b*NCg + nc)*Bg + (c - ALPHAg))*KBg + k]
                + (0.1f/32.f) * dot;
        dout[OFF_HEBB + (((b*NCg + nc)*Bg + (c - ALPHAg))*KBg + k)] = v;
    }
}

// readout[b, nc*32+d] = mean over c in [240,256) of msg[b,nc,c,d]
__global__ void readout_kernel(float* __restrict__ dout)
{
    int idx = blockIdx.x * 256 + threadIdx.x;
    if (idx >= BSg*NCg*Dg) return;
    int d = idx & 31, nc = (idx >> 5) & 63, b = idx >> 11;
    const float* msg = dout + OFF_MSG;
    int base = ((b*NCg + nc)*Cg + (Cg - ALPHAg))*Dg + d;
    float ssum = 0.f;
    #pragma unroll
    for (int t = 0; t < ALPHAg; ++t) ssum += msg[base + t*Dg];
    dout[OFF_READOUT + idx] = ssum * (1.f/ALPHAg);
}

extern "C" void kernel_launch(void* const* d_in, const int* in_sizes, int n_in,
                              void* d_out, int out_size)
{
    (void)in_sizes; (void)n_in; (void)out_size;
    const float* x           = (const float*)d_in[0];
    const float* h_in        = (const float*)d_in[1];
    const float* prevmsg     = (const float*)d_in[2];
    const float* decay_logit = (const float*)d_in[3];
    const float* prim        = (const float*)d_in[4];
    const float* heb_tr      = (const float*)d_in[5];
    const float* heb_trb     = (const float*)d_in[6];
    const float* state_w1    = (const float*)d_in[7];
    const float* state_b1    = (const float*)d_in[8];
    const float* state_w2    = (const float*)d_in[9];
    const float* state_b2    = (const float*)d_in[10];
    const float* msg_w1      = (const float*)d_in[11];
    const float* msg_b1      = (const float*)d_in[12];
    const float* msg_w2      = (const float*)d_in[13];
    const float* msg_b2      = (const float*)d_in[14];
    const float* mod_w1      = (const float*)d_in[15];
    const float* mod_b1      = (const float*)d_in[16];
    const float* mod_w2      = (const float*)d_in[17];
    const float* mod_b2      = (const float*)d_in[18];
    const float* neuron_id   = (const float*)d_in[19];
    const int*   conn_idx    = (const int*)d_in[20];
    const int*   bconn_idx   = (const int*)d_in[21];
    float* dout = (float*)d_out;

    cudaFuncSetAttribute(cell_kernel,
                         cudaFuncAttributeMaxDynamicSharedMemorySize,
                         (int)sizeof(Smem));

    cell_kernel<<<NTOT, 256, sizeof(Smem)>>>(
        x, h_in, prevmsg, decay_logit, prim, heb_tr, heb_trb,
        state_w1, state_b1, state_w2, state_b2,
        msg_w1, msg_b1, msg_w2, msg_b2,
        mod_w1, mod_b1, mod_w2, mod_b2,
        neuron_id, conn_idx, bconn_idx, dout);

    readout_kernel<<<(BSg*NCg*Dg + 255)/256, 256>>>(dout);
}

// round 2
// speedup vs baseline: 2.3161x; 2.3161x over previous
#include <cuda_runtime.h>
#include <math.h>

// Problem constants
#define NCg    64
#define Cg     256
#define Dg     32
#define Kg     16
#define KBg    16
#define ALPHAg 16
#define Bg     16
#define HSg    128
#define HMg    128
#define HMODg  32
#define BSg    8
#define NTOT   (NCg*Cg)          // 16384
#define MODIN  113
#define MODINP 116
#define MODOUT 65
#define MODOUTP 68
#define P1     97                // w1 row pitch (97 mod 32 == 1 -> conflict-free scalar col reads)
#define P2     132               // w2 / hbuf row pitch (132 mod 32 == 4 -> optimal float4 reads)

// Output layout: readout | h_new | msg | heb | heb_b
#define OFF_READOUT 0
#define OFF_HNEW   (BSg*NCg*Dg)
#define OFF_MSG    (OFF_HNEW + BSg*NTOT*Dg)
#define OFF_HEB    (OFF_MSG  + BSg*NTOT*Dg)
#define OFF_HEBB   (OFF_HEB  + BSg*NTOT*Kg)

struct __align__(16) Smem {
    float wt[HSg*P1];            // 12416 f: staged w1 (state/msg) OR w2 [32][P2]
    float part[2*BSg*P2];        // 2112 f : layer-1 partials; part[0..] doubles as hbuf
    float in[BSg*MODINP];        // 928  f : mod_input rows, zero-padded
    float modw1[HMODg*MODINP];   // 3712 f
    float modw2[HMODg*MODOUTP];  // 2176 f
    float b2m[MODOUTP];          // 68   f : mod_b2 padded
    float hid[HMODg*BSg];        // 256  f : mod hidden, [o][b]
    float outb[BSg*MODOUTP];     // 544  f : mod output, [b][68]
    float xt[97*BSg + 8];        // 784  f : transposed MLP input  xt[i*8 + b]
    float wsig[BSg*Kg];
    float wsigb[BSg*KBg];
    float msg[BSg*33];
    int   conn[Kg];
    int   bconn[KBg];
};  // ~94.2 KB -> 2 blocks/SM

__device__ __forceinline__ float sigmoidf_(float x) {
    return 1.f / (1.f + __expf(-x));
}

// Layer-1 MLP: hid[b][h] = tanh( sum_i wt[h][i] * xt[i][b] + bias[h] ),  h in [0,128)
// warp w: hq = w&3 (h-quarter), ih = w>>2 (i-half). lane -> h = hq*32+lane.
// Each thread keeps 8 batch accumulators in registers (weight reuse x8).
// Result written to s.part[0..] (= hbuf), pitch P2.
__device__ __forceinline__ void mlp_l1(Smem& s, int tid, int NI,
                                       const float* __restrict__ bias)
{
    const int w = tid >> 5, lane = tid & 31;
    const int hq = w & 3, ih = w >> 2;
    const int h = hq*32 + lane;
    const int half = (NI + 1) >> 1;
    const int i0 = ih ? half : 0;
    const int i1 = ih ? NI : half;
    float a0=0.f,a1=0.f,a2=0.f,a3=0.f,a4=0.f,a5=0.f,a6=0.f,a7=0.f;
    const float* wrow = s.wt + h*P1;
    #pragma unroll 4
    for (int i = i0; i < i1; ++i) {
        float wv = wrow[i];                                   // conflict-free (stride 97)
        float4 xa = *(const float4*)(s.xt + i*8);             // broadcast
        float4 xb = *(const float4*)(s.xt + i*8 + 4);         // broadcast
        a0 = fmaf(wv, xa.x, a0); a1 = fmaf(wv, xa.y, a1);
        a2 = fmaf(wv, xa.z, a2); a3 = fmaf(wv, xa.w, a3);
        a4 = fmaf(wv, xb.x, a4); a5 = fmaf(wv, xb.y, a5);
        a6 = fmaf(wv, xb.z, a6); a7 = fmaf(wv, xb.w, a7);
    }
    float* pp = s.part + ih*(BSg*P2) + h;                     // stride-1 stores, no conflicts
    pp[0*P2]=a0; pp[1*P2]=a1; pp[2*P2]=a2; pp[3*P2]=a3;
    pp[4*P2]=a4; pp[5*P2]=a5; pp[6*P2]=a6; pp[7*P2]=a7;
    __syncthreads();
    // reduce two halves + bias + tanh -> part[0] (hbuf)
    const int b = tid >> 5;
    const int h4 = (tid & 31) * 4;
    float4 v0 = *(const float4*)(s.part + b*P2 + h4);
    float4 v1 = *(const float4*)(s.part + BSg*P2 + b*P2 + h4);
    float4 bb = *(const float4*)(bias + h4);
    float4 r;
    r.x = tanhf(v0.x + v1.x + bb.x);
    r.y = tanhf(v0.y + v1.y + bb.y);
    r.z = tanhf(v0.z + v1.z + bb.z);
    r.w = tanhf(v0.w + v1.w + bb.w);
    *(float4*)(s.part + b*P2 + h4) = r;   // same addr each thread read -> no hazard
}

// Layer-2: acc[b][d] = bias2[d] + sum_h hbuf[b][h] * wt[d][h]   (wt staged [32][P2])
// lane = dsub*8 + b ; d = warp*4 + dsub. Weight rows broadcast across 8 lanes.
__device__ __forceinline__ float mlp_l2(const Smem& s, int tid,
                                        const float* __restrict__ bias2,
                                        int& b_out, int& d_out)
{
    const int w = tid >> 5, lane = tid & 31;
    const int b = lane & 7, dsub = lane >> 3;
    const int d = w*4 + dsub;
    float acc = bias2[d];
    const float4* w4 = (const float4*)(s.wt   + d*P2);
    const float4* h4 = (const float4*)(s.part + b*P2);
    #pragma unroll
    for (int j = 0; j < HSg/4; ++j) {
        float4 wv = w4[j]; float4 hv = h4[j];
        acc = fmaf(wv.x, hv.x, acc); acc = fmaf(wv.y, hv.y, acc);
        acc = fmaf(wv.z, hv.z, acc); acc = fmaf(wv.w, hv.w, acc);
    }
    b_out = b; d_out = d;
    return acc;
}

// stage a [32][128] global matrix into s.wt with pitch P2 (float4, coalesced)
__device__ __forceinline__ void stage_w2(Smem& s, int tid, const float* __restrict__ g)
{
    for (int idx4 = tid; idx4 < (32*128)/4; idx4 += 256) {
        int dd = idx4 >> 5, j = idx4 & 31;
        *(float4*)(s.wt + dd*P2 + 4*j) = ((const float4*)g)[idx4];
    }
}

__global__ void __launch_bounds__(256, 2)
cell_kernel(const float* __restrict__ x,
            const float* __restrict__ h_in,
            const float* __restrict__ prevmsg,
            const float* __restrict__ decay_logit,
            const float* __restrict__ prim,
            const float* __restrict__ heb_tr,
            const float* __restrict__ heb_trb,
            const float* __restrict__ state_w1, const float* __restrict__ state_b1,
            const float* __restrict__ state_w2, const float* __restrict__ state_b2,
            const float* __restrict__ msg_w1,  const float* __restrict__ msg_b1,
            const float* __restrict__ msg_w2,  const float* __restrict__ msg_b2,
            const float* __restrict__ mod_w1,  const float* __restrict__ mod_b1,
            const float* __restrict__ mod_w2,  const float* __restrict__ mod_b2,
            const float* __restrict__ neuron_id,
            const int*   __restrict__ conn_idx,
            const int*   __restrict__ bconn_idx,
            float* __restrict__ dout)
{
    extern __shared__ char smraw[];
    Smem& s = *reinterpret_cast<Smem*>(smraw);
    const int tid = threadIdx.x;
    const int n  = blockIdx.x;
    const int nc = n >> 8;
    const int c  = n & 255;
    const bool bord = (c >= ALPHAg) && (c < ALPHAg + Bg);

    // ---------------- Phase A: stage everything ----------------------------------------
    // mod_input rows (b-major, pitch 116, zero pad)
    for (int idx = tid; idx < BSg*MODINP; idx += 256) {
        int b = idx / MODINP, i = idx - b*MODINP;
        int base = ((b*NCg + nc)*Cg + c);
        float v = 0.f;
        if (i < Kg)       v = heb_tr[base*Kg + i];
        else if (i < 48)  { int d = i - 16; v = h_in[base*Dg + d];
                            if (c < ALPHAg) v += x[b*(NCg*Dg) + nc*Dg + d]; }
        else if (i == 48) v = decay_logit[base];
        else if (i < 81)  v = prim[base*Dg + (i-49)];
        else if (i < MODIN) v = neuron_id[(nc*Cg+c)*Dg + (i-81)];
        s.in[idx] = v;
    }
    for (int idx = tid; idx < HMODg*MODINP; idx += 256) {
        int o = idx / MODINP, i = idx - o*MODINP;
        s.modw1[idx] = (i < MODIN) ? mod_w1[(n*HMODg + o)*MODIN + i] : 0.f;
    }
    for (int idx = tid; idx < HMODg*MODOUTP; idx += 256) {
        int o = idx / MODOUTP, j = idx - o*MODOUTP;
        s.modw2[idx] = (j < MODOUT) ? mod_w2[(n*HMODg + o)*MODOUT + j] : 0.f;
    }
    if (tid < MODOUTP) s.b2m[tid] = (tid < MODOUT) ? mod_b2[n*MODOUT + tid] : 0.f;
    if (tid >= 192 && tid < 192+Kg) s.conn[tid-192] = conn_idx[(nc*Cg+c)*Kg + (tid-192)];
    if (bord && tid >= 224 && tid < 224+KBg)
        s.bconn[tid-224] = bconn_idx[(nc*Bg + (c-ALPHAg))*KBg + (tid-224)];
    // stage state_w1 (flat copy, natural pitch 97)
    for (int idx4 = tid; idx4 < (HSg*P1)/4; idx4 += 256)
        ((float4*)s.wt)[idx4] = ((const float4*)state_w1)[idx4];
    __syncthreads();  // S1

    // ---------------- Phase D: gather neighbors into REGISTERS -------------------------
    const int fb = tid >> 5, fd = tid & 31;   // (b, d) thread map for D/F/K
    float nr[Kg];
    #pragma unroll
    for (int k = 0; k < Kg; ++k)
        nr[k] = prevmsg[((fb*NCg + nc)*Cg + s.conn[k])*Dg + fd];
    float bnr[KBg];
    if (bord) {
        #pragma unroll
        for (int k = 0; k < KBg; ++k) {
            int j = s.bconn[k];
            bnr[k] = prevmsg[((fb*NCg + (j >> 4))*Cg + ALPHAg + (j & 15))*Dg + fd];
        }
    }

    // ---------------- Phase B: mod hidden = tanh(modw1 @ in + b1) ----------------------
    {
        int o = tid >> 3, b = tid & 7;
        float acc = mod_b1[n*HMODg + o];
        const float4* w4 = (const float4*)(s.modw1 + o*MODINP);
        const float4* x4 = (const float4*)(s.in    + b*MODINP);
        #pragma unroll
        for (int j = 0; j < MODINP/4; ++j) {
            float4 w = w4[j]; float4 xx = x4[j];
            acc = fmaf(w.x, xx.x, acc); acc = fmaf(w.y, xx.y, acc);
            acc = fmaf(w.z, xx.z, acc); acc = fmaf(w.w, xx.w, acc);
        }
        s.hid[o*BSg + b] = tanhf(acc);      // [o][b] layout: conflict-free store
    }
    __syncthreads();  // S2

    // ---------------- Phase C: outb = hid @ modw2 + b2  (float4 over outputs) ----------
    if (tid < 136) {
        int b = tid / 17, og = tid % 17;
        float4 acc = *(const float4*)(s.b2m + og*4);
        #pragma unroll
        for (int hh = 0; hh < HMODg; ++hh) {
            float hv = s.hid[hh*BSg + b];
            float4 w = *(const float4*)(s.modw2 + hh*MODOUTP + og*4);
            acc.x = fmaf(hv, w.x, acc.x); acc.y = fmaf(hv, w.y, acc.y);
            acc.z = fmaf(hv, w.z, acc.z); acc.w = fmaf(hv, w.w, acc.w);
        }
        *(float4*)(s.outb + b*MODOUTP + og*4) = acc;
    }
    __syncthreads();  // S3

    // ---------------- Phase E: w_sig, xt (h / prim / decay) ----------------------------
    if (tid < 128) {
        int b = tid >> 4, k = tid & 15;
        s.wsig[b*Kg + k] = sigmoidf_(s.outb[b*MODOUTP + k] + s.in[b*MODINP + k]);
    } else if (bord) {
        int t = tid - 128; int b = t >> 4, k = t & 15;
        s.wsigb[b*KBg + k] = sigmoidf_(s.outb[b*MODOUTP + 16 + k]
                          + heb_trb[((b*NCg + nc)*Bg + (c - ALPHAg))*KBg + k]);
    }
    {   // xt rows 0..31 = h
        int i = tid >> 3, b = tid & 7;
        s.xt[i*8 + b] = s.in[b*MODINP + 16 + i];
    }
    for (int idx = tid; idx < 264; idx += 256) {  // rows 64..95 = prim, 96 = decay
        int i = idx >> 3, b = idx & 7;
        float v = (i < 32) ? s.outb[b*MODOUTP + 33 + i] : s.outb[b*MODOUTP + 32];
        s.xt[(64 + i)*8 + b] = v;
    }
    __syncthreads();  // S4

    // ---------------- Phase F: agg (register neigh) -> xt rows 32..63 ------------------
    {
        float acc = 0.f;
        #pragma unroll
        for (int k = 0; k < Kg; ++k) acc = fmaf(s.wsig[fb*Kg + k], nr[k], acc);
        if (bord) {
            #pragma unroll
            for (int k = 0; k < KBg; ++k) acc = fmaf(s.wsigb[fb*KBg + k], bnr[k], acc);
        }
        s.xt[(32 + fd)*8 + fb] = acc;
    }
    __syncthreads();  // S5

    // ---------------- Phase G: shid -> hbuf ---------------------------------------------
    mlp_l1(s, tid, 97, state_b1);            // internal S6
    stage_w2(s, tid, state_w2);              // wt now dead for w1, stage state_w2
    __syncthreads();  // S7

    // ---------------- Phase H: delta, h_new ---------------------------------------------
    {
        int b, d;
        float acc = mlp_l2(s, tid, state_b2, b, d);
        float dec = sigmoidf_(s.outb[b*MODOUTP + 32]);
        float hv  = s.in[b*MODINP + 16 + d];
        float hn  = dec*hv + (1.f - dec)*tanhf(acc);
        s.xt[d*8 + b] = hn;
        dout[OFF_HNEW + (((b*NCg + nc)*Cg + c)*Dg + d)] = hn;
    }
    {   // xt rows 64..95 = nid (replaces prim)
        int i = tid >> 3, b = tid & 7;
        s.xt[(64 + i)*8 + b] = s.in[b*MODINP + 81 + i];
    }
    __syncthreads();  // S8

    // stage msg_w1 into wt (rows 96 -> pitch 97)
    for (int idx = tid; idx < HMg*96; idx += 256) {
        int hh = idx / 96, i = idx - hh*96;
        s.wt[hh*P1 + i] = msg_w1[idx];
    }
    __syncthreads();  // S9

    // ---------------- Phase I: mhid -> hbuf ---------------------------------------------
    mlp_l1(s, tid, 96, msg_b1);              // internal S10
    stage_w2(s, tid, msg_w2);
    __syncthreads();  // S11

    // ---------------- Phase J: msg -------------------------------------------------------
    {
        int b, d;
        float acc = mlp_l2(s, tid, msg_b2, b, d);
        s.msg[b*33 + d] = acc;
        dout[OFF_MSG + (((b*NCg + nc)*Cg + c)*Dg + d)] = acc;
    }
    __syncthreads();  // S12

    // ---------------- Phase K: Hebbian via warp reductions -------------------------------
    {
        float msgv = s.msg[fb*33 + fd];
        float dotk = 0.f;
        #pragma unroll
        for (int k = 0; k < Kg; ++k) {
            float t = msgv * nr[k];
            t += __shfl_xor_sync(0xffffffffu, t, 16);
            t += __shfl_xor_sync(0xffffffffu, t, 8);
            t += __shfl_xor_sync(0xffffffffu, t, 4);
            t += __shfl_xor_sync(0xffffffffu, t, 2);
            t += __shfl_xor_sync(0xffffffffu, t, 1);
            if (fd == k) dotk = t;
        }
        if (fd < Kg) {
            float v = 0.9f * s.in[fb*MODINP + fd] + 0.003125f * dotk;
            dout[OFF_HEB + (((fb*NCg + nc)*Cg + c)*Kg + fd)] = v;
        }
        if (bord) {
            float bdotk = 0.f;
            #pragma unroll
            for (int k = 0; k < KBg; ++k) {
                float t = msgv * bnr[k];
                t += __shfl_xor_sync(0xffffffffu, t, 16);
                t += __shfl_xor_sync(0xffffffffu, t, 8);
                t += __shfl_xor_sync(0xffffffffu, t, 4);
                t += __shfl_xor_sync(0xffffffffu, t, 2);
                t += __shfl_xor_sync(0xffffffffu, t, 1);
                if (fd == k) bdotk = t;
            }
            if (fd < KBg) {
                float v = 0.9f * heb_trb[((fb*NCg + nc)*Bg + (c - ALPHAg))*KBg + fd]
                        + 0.003125f * bdotk;
                dout[OFF_HEBB + (((fb*NCg + nc)*Bg + (c - ALPHAg))*KBg + fd)] = v;
            }
        }
    }
}

// readout[b, nc*32+d] = mean over c in [240,256) of msg[b,nc,c,d]
__global__ void readout_kernel(float* __restrict__ dout)
{
    int idx = blockIdx.x * 256 + threadIdx.x;
    if (idx >= BSg*NCg*Dg) return;
    int d = idx & 31, nc = (idx >> 5) & 63, b = idx >> 11;
    const float* msg = dout + OFF_MSG;
    int base = ((b*NCg + nc)*Cg + (Cg - ALPHAg))*Dg + d;
    float ssum = 0.f;
    #pragma unroll
    for (int t = 0; t < ALPHAg; ++t) ssum += msg[base + t*Dg];
    dout[OFF_READOUT + idx] = ssum * (1.f/ALPHAg);
}

extern "C" void kernel_launch(void* const* d_in, const int* in_sizes, int n_in,
                              void* d_out, int out_size)
{
    (void)in_sizes; (void)n_in; (void)out_size;
    const float* x           = (const float*)d_in[0];
    const float* h_in        = (const float*)d_in[1];
    const float* prevmsg     = (const float*)d_in[2];
    const float* decay_logit = (const float*)d_in[3];
    const float* prim        = (const float*)d_in[4];
    const float* heb_tr      = (const float*)d_in[5];
    const float* heb_trb     = (const float*)d_in[6];
    const float* state_w1    = (const float*)d_in[7];
    const float* state_b1    = (const float*)d_in[8];
    const float* state_w2    = (const float*)d_in[9];
    const float* state_b2    = (const float*)d_in[10];
    const float* msg_w1      = (const float*)d_in[11];
    const float* msg_b1      = (const float*)d_in[12];
    const float* msg_w2      = (const float*)d_in[13];
    const float* msg_b2      = (const float*)d_in[14];
    const float* mod_w1      = (const float*)d_in[15];
    const float* mod_b1      = (const float*)d_in[16];
    const float* mod_w2      = (const float*)d_in[17];
    const float* mod_b2      = (const float*)d_in[18];
    const float* neuron_id   = (const float*)d_in[19];
    const int*   conn_idx    = (const int*)d_in[20];
    const int*   bconn_idx   = (const int*)d_in[21];
    float* dout = (float*)d_out;

    cudaFuncSetAttribute(cell_kernel,
                         cudaFuncAttributeMaxDynamicSharedMemorySize,
                         (int)sizeof(Smem));

    cell_kernel<<<NTOT, 256, sizeof(Smem)>>>(
        x, h_in, prevmsg, decay_logit, prim, heb_tr, heb_trb,
        state_w1, state_b1, state_w2, state_b2,
        msg_w1, msg_b1, msg_w2, msg_b2,
        mod_w1, mod_b1, mod_w2, mod_b2,
        neuron_id, conn_idx, bconn_idx, dout);

    readout_kernel<<<(BSg*NCg*Dg + 255)/256, 256>>>(dout);
}